// round 4
// baseline (speedup 1.0000x reference)
#include <cuda_runtime.h>
#include <cstdint>

// Q = L @ L^T, L lower-triangular 3x3 from packed [a,b,c,d,e,f]:
//   Q00=a*a  Q01=a*b      Q02=a*d
//   Q10=a*b  Q11=b*b+c*c  Q12=b*d+c*e
//   Q20=a*d  Q21=b*d+c*e  Q22=d*d+e*e+f*f
//
// Persistent-style grid-stride kernel, 256-row tiles, cp.async.cg (LDGSTS,
// L1-bypass) double-buffered input so each block keeps a global load group
// in flight while computing/storing the previous tile. Stores are dense
// STG.128 from a smem-staged output tile.

#define TPB 128
#define ROWS_PB 256
#define IN_F4 (ROWS_PB * 6 / 4)    // 384 float4 per tile -> 3 per thread
#define OUT_F4 (ROWS_PB * 9 / 4)   // 576 float4 per tile -> 4.5 per thread

__device__ __forceinline__ void cp_async16(uint32_t saddr, const void* gaddr) {
    asm volatile("cp.async.cg.shared.global [%0], [%1], 16;\n" :: "r"(saddr), "l"(gaddr));
}
__device__ __forceinline__ void cp_commit() {
    asm volatile("cp.async.commit_group;\n" ::: "memory");
}
template <int N>
__device__ __forceinline__ void cp_wait() {
    asm volatile("cp.async.wait_group %0;\n" :: "n"(N) : "memory");
}

__device__ __forceinline__ void row_to_q(const float* __restrict__ v, float* __restrict__ o) {
    const float a = v[0], b = v[1], c = v[2], d = v[3], e = v[4], f = v[5];
    const float ab = a * b;
    const float ad = a * d;
    const float bdce = fmaf(b, d, c * e);
    o[0] = a * a;
    o[1] = ab;
    o[2] = ad;
    o[3] = ab;
    o[4] = fmaf(b, b, c * c);
    o[5] = bdce;
    o[6] = ad;
    o[7] = bdce;
    o[8] = fmaf(d, d, fmaf(e, e, f * f));
}

__global__ __launch_bounds__(TPB) void chol_to_cov_pipe(const float4* __restrict__ in4,
                                                        float4* __restrict__ out4,
                                                        int num_tiles)
{
    __shared__ float4 s_in[2][IN_F4];      // 2 x 6 KB
    __shared__ float  s_out[ROWS_PB * 9];  // 9 KB

    const int t = threadIdx.x;
    const int G = gridDim.x;

    int tile = blockIdx.x;
    if (tile >= num_tiles) return;

    // Prologue: issue loads for first tile into buffer 0.
    {
        const float4* ip = in4 + (size_t)tile * IN_F4;
        uint32_t sbase = (uint32_t)__cvta_generic_to_shared(&s_in[0][0]);
#pragma unroll
        for (int k = 0; k < 3; k++)
            cp_async16(sbase + (t + TPB * k) * 16u, ip + t + TPB * k);
        cp_commit();
    }

    int s = 0;
    while (tile < num_tiles) {
        const int next = tile + G;
        if (next < num_tiles) {
            // Issue loads for next tile into the other buffer, then wait for
            // the oldest group (current tile) while next stays in flight.
            const float4* ip = in4 + (size_t)next * IN_F4;
            uint32_t sbase = (uint32_t)__cvta_generic_to_shared(&s_in[s ^ 1][0]);
#pragma unroll
            for (int k = 0; k < 3; k++)
                cp_async16(sbase + (t + TPB * k) * 16u, ip + t + TPB * k);
            cp_commit();
            cp_wait<1>();
        } else {
            cp_wait<0>();
        }
        // Barrier: input tile visible to all; also guarantees every thread
        // finished its store-phase LDS of s_out from the previous iteration
        // before we overwrite s_out below.
        __syncthreads();

        // Compute 2 rows per thread from s_in[s] into s_out.
        const float* sif = reinterpret_cast<const float*>(&s_in[s][0]);
#pragma unroll
        for (int j = 0; j < 2; j++) {
            const int r = t + TPB * j;
            float v[6], o[9];
#pragma unroll
            for (int k = 0; k < 6; k++) v[k] = sif[r * 6 + k];
            row_to_q(v, o);
#pragma unroll
            for (int k = 0; k < 9; k++) s_out[r * 9 + k] = o[k];
        }
        __syncthreads();

        // Dense coalesced store smem -> gmem (4 full STG.128 + half iteration).
        float4* op = out4 + (size_t)tile * OUT_F4;
        const float4* so4 = reinterpret_cast<const float4*>(s_out);
#pragma unroll
        for (int k = 0; k < 4; k++)
            __stcs(op + t + TPB * k, so4[t + TPB * k]);
        if (t < OUT_F4 - 4 * TPB)
            __stcs(op + t + 4 * TPB, so4[t + 4 * TPB]);

        s ^= 1;
        tile = next;
    }
}

// Scalar tail for the (< ROWS_PB) remainder rows.
__global__ void chol_to_cov_tail(const float* __restrict__ in,
                                 float* __restrict__ out,
                                 int start_row, int n_rows)
{
    const int r = start_row + blockIdx.x * blockDim.x + threadIdx.x;
    if (r >= n_rows) return;
    float v[6], o[9];
#pragma unroll
    for (int k = 0; k < 6; k++) v[k] = in[(size_t)r * 6 + k];
    row_to_q(v, o);
#pragma unroll
    for (int k = 0; k < 9; k++) out[(size_t)r * 9 + k] = o[k];
}

extern "C" void kernel_launch(void* const* d_in, const int* in_sizes, int n_in,
                              void* d_out, int out_size)
{
    const float* in = (const float*)d_in[0];
    float* out = (float*)d_out;
    const int n_rows = in_sizes[0] / 6;

    const int num_tiles = n_rows / ROWS_PB;
    if (num_tiles > 0) {
        // ~10 blocks/SM (21 KB smem each); GB300 has 152 SMs.
        int grid = 152 * 10;
        if (grid > num_tiles) grid = num_tiles;
        chol_to_cov_pipe<<<grid, TPB>>>((const float4*)in, (float4*)out, num_tiles);
    }
    const int done = num_tiles * ROWS_PB;
    if (done < n_rows) {
        const int rem = n_rows - done;
        chol_to_cov_tail<<<(rem + 127) / 128, 128>>>(in, out, done, n_rows);
    }
}

// round 5
// speedup vs baseline: 1.1474x; 1.1474x over previous
#include <cuda_runtime.h>
#include <cstdint>

// Q = L @ L^T, L lower-triangular 3x3 from packed [a,b,c,d,e,f]:
//   Q00=a*a  Q01=a*b      Q02=a*d
//   Q10=a*b  Q11=b*b+c*c  Q12=b*d+c*e
//   Q20=a*d  Q21=b*d+c*e  Q22=d*d+e*e+f*f
//
// Non-persistent hybrid: each block owns 2 consecutive 256-row tiles.
// Both tiles' input loads are issued via cp.async.cg (LDGSTS, L1-bypass)
// at block start (6 outstanding 16B copies per thread), then tile0 is
// computed/stored while tile1's loads stream in. Dense STG.128 stores
// from an smem-staged output tile with streaming (evict-first) hint.

#define TPB 128
#define ROWS_PB 256
#define IN_F4 (ROWS_PB * 6 / 4)    // 384 float4 per tile -> 3 per thread
#define OUT_F4 (ROWS_PB * 9 / 4)   // 576 float4 per tile -> 4.5 per thread

__device__ __forceinline__ void cp_async16(uint32_t saddr, const void* gaddr) {
    asm volatile("cp.async.cg.shared.global [%0], [%1], 16;\n" :: "r"(saddr), "l"(gaddr));
}
__device__ __forceinline__ void cp_commit() {
    asm volatile("cp.async.commit_group;\n" ::: "memory");
}
template <int N>
__device__ __forceinline__ void cp_wait() {
    asm volatile("cp.async.wait_group %0;\n" :: "n"(N) : "memory");
}

__device__ __forceinline__ void row_to_q(const float* __restrict__ v, float* __restrict__ o) {
    const float a = v[0], b = v[1], c = v[2], d = v[3], e = v[4], f = v[5];
    const float ab = a * b;
    const float ad = a * d;
    const float bdce = fmaf(b, d, c * e);
    o[0] = a * a;
    o[1] = ab;
    o[2] = ad;
    o[3] = ab;
    o[4] = fmaf(b, b, c * c);
    o[5] = bdce;
    o[6] = ad;
    o[7] = bdce;
    o[8] = fmaf(d, d, fmaf(e, e, f * f));
}

__device__ __forceinline__ void compute_tile(const float4* __restrict__ sin,
                                             float* __restrict__ s_out, int t)
{
    const float* sif = reinterpret_cast<const float*>(sin);
#pragma unroll
    for (int j = 0; j < 2; j++) {
        const int r = t + TPB * j;
        float v[6], o[9];
#pragma unroll
        for (int k = 0; k < 6; k++) v[k] = sif[r * 6 + k];
        row_to_q(v, o);
#pragma unroll
        for (int k = 0; k < 9; k++) s_out[r * 9 + k] = o[k];
    }
}

__device__ __forceinline__ void store_tile(float4* __restrict__ op,
                                           const float* __restrict__ s_out, int t)
{
    const float4* so4 = reinterpret_cast<const float4*>(s_out);
#pragma unroll
    for (int k = 0; k < 4; k++)
        __stcs(op + t + TPB * k, so4[t + TPB * k]);
    if (t < OUT_F4 - 4 * TPB)  // remaining 64 float4
        __stcs(op + t + 4 * TPB, so4[t + 4 * TPB]);
}

__global__ __launch_bounds__(TPB) void chol_to_cov_2tile(const float4* __restrict__ in4,
                                                         float4* __restrict__ out4,
                                                         int num_tiles)
{
    __shared__ float4 s_in[2][IN_F4];      // 12 KB
    __shared__ float  s_out[ROWS_PB * 9];  // 9 KB

    const int t = threadIdx.x;
    const int tile0 = blockIdx.x * 2;
    const int tile1 = tile0 + 1;
    const bool has1 = (tile1 < num_tiles);

    // Issue ALL input loads up-front: tile0 -> group 0, tile1 -> group 1.
    {
        const float4* ip0 = in4 + (size_t)tile0 * IN_F4;
        uint32_t sb0 = (uint32_t)__cvta_generic_to_shared(&s_in[0][0]);
#pragma unroll
        for (int k = 0; k < 3; k++)
            cp_async16(sb0 + (t + TPB * k) * 16u, ip0 + t + TPB * k);
        cp_commit();
        if (has1) {
            const float4* ip1 = in4 + (size_t)tile1 * IN_F4;
            uint32_t sb1 = (uint32_t)__cvta_generic_to_shared(&s_in[1][0]);
#pragma unroll
            for (int k = 0; k < 3; k++)
                cp_async16(sb1 + (t + TPB * k) * 16u, ip1 + t + TPB * k);
            cp_commit();
        }
    }

    // Tile 0: wait only for group 0 (group 1 keeps streaming).
    if (has1) cp_wait<1>(); else cp_wait<0>();
    __syncthreads();
    compute_tile(s_in[0], s_out, t);
    __syncthreads();
    store_tile(out4 + (size_t)tile0 * OUT_F4, s_out, t);

    if (has1) {
        cp_wait<0>();
        // Barrier: tile1 input visible AND all store-phase LDS of s_out done.
        __syncthreads();
        compute_tile(s_in[1], s_out, t);
        __syncthreads();
        store_tile(out4 + (size_t)tile1 * OUT_F4, s_out, t);
    }
}

// Scalar tail for the (< ROWS_PB) remainder rows.
__global__ void chol_to_cov_tail(const float* __restrict__ in,
                                 float* __restrict__ out,
                                 int start_row, int n_rows)
{
    const int r = start_row + blockIdx.x * blockDim.x + threadIdx.x;
    if (r >= n_rows) return;
    float v[6], o[9];
#pragma unroll
    for (int k = 0; k < 6; k++) v[k] = in[(size_t)r * 6 + k];
    row_to_q(v, o);
#pragma unroll
    for (int k = 0; k < 9; k++) out[(size_t)r * 9 + k] = o[k];
}

extern "C" void kernel_launch(void* const* d_in, const int* in_sizes, int n_in,
                              void* d_out, int out_size)
{
    const float* in = (const float*)d_in[0];
    float* out = (float*)d_out;
    const int n_rows = in_sizes[0] / 6;

    const int num_tiles = n_rows / ROWS_PB;
    if (num_tiles > 0) {
        const int blocks = (num_tiles + 1) / 2;
        chol_to_cov_2tile<<<blocks, TPB>>>((const float4*)in, (float4*)out, num_tiles);
    }
    const int done = num_tiles * ROWS_PB;
    if (done < n_rows) {
        const int rem = n_rows - done;
        chol_to_cov_tail<<<(rem + 127) / 128, 128>>>(in, out, done, n_rows);
    }
}

// round 6
// speedup vs baseline: 1.1568x; 1.0082x over previous
#include <cuda_runtime.h>
#include <cstdint>

// Q = L @ L^T, L lower-triangular 3x3 from packed [a,b,c,d,e,f]:
//   Q00=a*a  Q01=a*b      Q02=a*d
//   Q10=a*b  Q11=b*b+c*c  Q12=b*d+c*e
//   Q20=a*d  Q21=b*d+c*e  Q22=d*d+e*e+f*f
//
// Warp-autonomous 2-tile pipeline. Each of the 4 warps owns a fully
// self-contained slice (64 rows per tile: 96 input float4, 144 output
// float4, all contiguous and warp-aligned), so NO __syncthreads is needed
// anywhere — only __syncwarp. Warps drift out of phase, interleaving their
// load/compute/store bursts and smoothing DRAM demand. Input loads for both
// tiles are issued up-front via cp.async.cg (6 outstanding 16B copies per
// thread); tile0 is computed/stored while tile1's loads stream.

#define TPB 128
#define ROWS_PB 256
#define IN_F4 (ROWS_PB * 6 / 4)    // 384 f4/tile ; per warp: 96 (3/lane)
#define OUT_F4 (ROWS_PB * 9 / 4)   // 576 f4/tile ; per warp: 144 (4.5/lane)
#define W_IN 96
#define W_OUT 144
#define W_ROWS 64

__device__ __forceinline__ void cp_async16(uint32_t saddr, const void* gaddr) {
    asm volatile("cp.async.cg.shared.global [%0], [%1], 16;\n" :: "r"(saddr), "l"(gaddr));
}
__device__ __forceinline__ void cp_commit() {
    asm volatile("cp.async.commit_group;\n" ::: "memory");
}
template <int N>
__device__ __forceinline__ void cp_wait() {
    asm volatile("cp.async.wait_group %0;\n" :: "n"(N) : "memory");
}

__device__ __forceinline__ void row_to_q(const float* __restrict__ v, float* __restrict__ o) {
    const float a = v[0], b = v[1], c = v[2], d = v[3], e = v[4], f = v[5];
    const float ab = a * b;
    const float ad = a * d;
    const float bdce = fmaf(b, d, c * e);
    o[0] = a * a;
    o[1] = ab;
    o[2] = ad;
    o[3] = ab;
    o[4] = fmaf(b, b, c * c);
    o[5] = bdce;
    o[6] = ad;
    o[7] = bdce;
    o[8] = fmaf(d, d, fmaf(e, e, f * f));
}

// Compute this warp's 64 rows of one tile: smem input slice -> smem output slice.
__device__ __forceinline__ void warp_compute(const float* __restrict__ sin_w,   // 64 rows * 6
                                             float* __restrict__ sout_w,        // 64 rows * 9
                                             int l)
{
#pragma unroll
    for (int j = 0; j < 2; j++) {
        const int r = l + 32 * j;
        float v[6], o[9];
#pragma unroll
        for (int k = 0; k < 6; k++) v[k] = sin_w[r * 6 + k];
        row_to_q(v, o);
#pragma unroll
        for (int k = 0; k < 9; k++) sout_w[r * 9 + k] = o[k];
    }
}

// Store this warp's 144 output float4 (dense, warp-coalesced, evict-first).
__device__ __forceinline__ void warp_store(float4* __restrict__ op_w,
                                           const float* __restrict__ sout_w, int l)
{
    const float4* so4 = reinterpret_cast<const float4*>(sout_w);
#pragma unroll
    for (int k = 0; k < 4; k++)
        __stcs(op_w + l + 32 * k, so4[l + 32 * k]);
    if (l < W_OUT - 128)  // remaining 16 float4
        __stcs(op_w + l + 128, so4[l + 128]);
}

__global__ __launch_bounds__(TPB) void chol_to_cov_warp2(const float4* __restrict__ in4,
                                                         float4* __restrict__ out4,
                                                         int num_tiles)
{
    __shared__ float4 s_in[2][IN_F4];      // 12 KB
    __shared__ float  s_out[ROWS_PB * 9];  // 9 KB (one tile; reused, warp-private slices)

    const int t = threadIdx.x;
    const int w = t >> 5;
    const int l = t & 31;

    const int tile0 = blockIdx.x * 2;
    const int tile1 = tile0 + 1;
    const bool has1 = (tile1 < num_tiles);

    // Issue this warp's input slice for both tiles: tile0 -> group0, tile1 -> group1.
    {
        const float4* ip0 = in4 + (size_t)tile0 * IN_F4 + w * W_IN;
        uint32_t sb0 = (uint32_t)__cvta_generic_to_shared(&s_in[0][w * W_IN]);
#pragma unroll
        for (int k = 0; k < 3; k++)
            cp_async16(sb0 + (l + 32 * k) * 16u, ip0 + l + 32 * k);
        cp_commit();
        if (has1) {
            const float4* ip1 = in4 + (size_t)tile1 * IN_F4 + w * W_IN;
            uint32_t sb1 = (uint32_t)__cvta_generic_to_shared(&s_in[1][w * W_IN]);
#pragma unroll
            for (int k = 0; k < 3; k++)
                cp_async16(sb1 + (l + 32 * k) * 16u, ip1 + l + 32 * k);
            cp_commit();
        }
    }

    const float* sin0_w = reinterpret_cast<const float*>(&s_in[0][w * W_IN]);
    const float* sin1_w = reinterpret_cast<const float*>(&s_in[1][w * W_IN]);
    float* sout_w = s_out + w * W_ROWS * 9;

    // ---- Tile 0 ----
    if (has1) cp_wait<1>(); else cp_wait<0>();
    __syncwarp();                       // all lanes' tile0 copies visible to warp
    warp_compute(sin0_w, sout_w, l);
    __syncwarp();                       // compute writes visible before store reads
    warp_store(out4 + (size_t)tile0 * OUT_F4 + w * W_OUT, sout_w, l);

    // ---- Tile 1 ----
    if (has1) {
        cp_wait<0>();
        __syncwarp();                   // tile1 copies visible; tile0 store reads done
        warp_compute(sin1_w, sout_w, l);
        __syncwarp();
        warp_store(out4 + (size_t)tile1 * OUT_F4 + w * W_OUT, sout_w, l);
    }
}

// Scalar tail for the (< ROWS_PB) remainder rows.
__global__ void chol_to_cov_tail(const float* __restrict__ in,
                                 float* __restrict__ out,
                                 int start_row, int n_rows)
{
    const int r = start_row + blockIdx.x * blockDim.x + threadIdx.x;
    if (r >= n_rows) return;
    float v[6], o[9];
#pragma unroll
    for (int k = 0; k < 6; k++) v[k] = in[(size_t)r * 6 + k];
    row_to_q(v, o);
#pragma unroll
    for (int k = 0; k < 9; k++) out[(size_t)r * 9 + k] = o[k];
}

extern "C" void kernel_launch(void* const* d_in, const int* in_sizes, int n_in,
                              void* d_out, int out_size)
{
    const float* in = (const float*)d_in[0];
    float* out = (float*)d_out;
    const int n_rows = in_sizes[0] / 6;

    const int num_tiles = n_rows / ROWS_PB;
    if (num_tiles > 0) {
        const int blocks = (num_tiles + 1) / 2;
        chol_to_cov_warp2<<<blocks, TPB>>>((const float4*)in, (float4*)out, num_tiles);
    }
    const int done = num_tiles * ROWS_PB;
    if (done < n_rows) {
        const int rem = n_rows - done;
        chol_to_cov_tail<<<(rem + 127) / 128, 128>>>(in, out, done, n_rows);
    }
}